// round 12
// baseline (speedup 1.0000x reference)
#include <cuda_runtime.h>
#include <cstddef>

// Problem constants (fixed by setup_inputs)
#define BB 2
#define DD 48
#define HH 320
#define WW 640
#define RR 2
#define KK 5
#define K2 25
#define HW (HH * WW)

// Tiling: 12x32 output tile, 192 threads, 2 vertical pixels per thread.
// 3 blocks/SM -> 18 warps; reg cap 65536/576 = 113 >= natural 106 (no shave).
// One D-chunk (24 disparities) per block; chunk is the fastest grid dim.
#define TH 12
#define TW 32
#define DC 24
#define NCHUNK (DD / DC)   // 2
#define PH (TH + 2 * RR)   // 16
#define PW (TW + 2 * RR)   // 36
#define PD (DC + 2)        // 26 planes used
#define PDP 28             // plane stride (112B -> conflict-free LDS.128)
#define NT 192
#define SMEM_BYTES (PH * PW * PDP * 4)   // 64512
#define GRID_Y ((HH + TH - 1) / TH)      // 27 (last tile ragged: 8 rows)

// Intermediate buffer for pass-1 result (allocation-free scratch)
__device__ float g_y[(size_t)BB * DD * HH * WW];

__device__ __forceinline__ unsigned long long pk2(float lo, float hi) {
    unsigned long long r;
    asm("mov.b64 %0, {%1, %2};" : "=l"(r) : "f"(lo), "f"(hi));
    return r;
}
__device__ __forceinline__ void ffma2(unsigned long long &acc,
                                      unsigned long long a,
                                      unsigned long long b) {
    asm("fma.rn.f32x2 %0, %1, %2, %0;" : "+l"(acc) : "l"(a), "l"(b));
}
__device__ __forceinline__ void upk2(unsigned long long v, float &lo, float &hi) {
    asm("mov.b64 {%0, %1}, %2;" : "=f"(lo), "=f"(hi) : "l"(v));
}

union Q4 { float4 f; unsigned long long u[2]; float s[4]; };
union Q2 { float2 f; unsigned long long u; float s[2]; };

// Load one flattened tap's 6 weights (3 for pixel0 row, 3 for pixel1 row).
// fi is compile-time under full unroll; invalid groups load nothing (stay 0).
__device__ __forceinline__ void load_tap(int fi, const float* wb0,
                                         const float* wb1, float* P)
{
    const int i = fi / KK;
    const int j = fi - i * KK;
    P[0] = 0.f; P[1] = 0.f; P[2] = 0.f; P[3] = 0.f; P[4] = 0.f; P[5] = 0.f;
    if (i < KK) {            // pixel0 tap (i, j)
        P[0] = __ldg(wb0 + (size_t)(0 * K2 + i * KK + j) * HW);
        P[1] = __ldg(wb0 + (size_t)(1 * K2 + i * KK + j) * HW);
        P[2] = __ldg(wb0 + (size_t)(2 * K2 + i * KK + j) * HW);
    }
    if (i >= 1) {            // pixel1 tap (i-1, j)
        P[3] = __ldg(wb1 + (size_t)(0 * K2 + (i - 1) * KK + j) * HW);
        P[4] = __ldg(wb1 + (size_t)(1 * K2 + (i - 1) * KK + j) * HW);
        P[5] = __ldg(wb1 + (size_t)(2 * K2 + (i - 1) * KK + j) * HW);
    }
}

__global__ void __launch_bounds__(NT, 3)
lga_kernel(const float* __restrict__ xin,
           const float* __restrict__ wts,
           float* __restrict__ xout)
{
    extern __shared__ float xs[];   // [PH][PW][PDP]

    const int t  = threadIdx.x;
    const int tx = t & 31;       // W within tile
    const int ty = t >> 5;       // 0..5 -> output rows 2ty, 2ty+1

    const int bx    = blockIdx.x;
    const int chunk = bx & 1;            // fastest dim: chunks of a tile adjacent
    const int w0p   = (bx >> 1) * TW;
    const int h0    = blockIdx.y * TH;
    const int b     = blockIdx.z;
    const int d0    = chunk * DC;

    const int gh0 = h0 + 2 * ty;
    const bool row0ok = (gh0 < HH);
    const bool row1ok = (gh0 + 1 < HH);
    // clamp weight-row addresses for the ragged last tile (values discarded)
    const int gh0c = row0ok ? gh0 : (HH - 1);
    const int gh1c = row1ok ? (gh0 + 1) : (HH - 1);
    const int gw  = w0p + tx;

    // weight base: wts[b, c, gh, gw], channel stride = HW
    const float* wb0 = wts + ((size_t)b * (3 * K2)) * HW + (size_t)gh0c * WW + gw;
    const float* wb1 = wts + ((size_t)b * (3 * K2)) * HW + (size_t)gh1c * WW + gw;

    // thread's column base in the slab; per-tap offset is a compile-time const
    float* const xsb = &xs[(2 * ty * PW + tx) * PDP];

    // ---- prime the 3-stage weight pipeline BEFORE the fill (overlap) ----
    float P[3][6];
    load_tap(0, wb0, wb1, P[0]);
    load_tap(1, wb0, wb1, P[1]);

    // ---- fill shared slab, plane-contiguous: xs[(row*PW+col)*PDP + p] ----
    for (int pos = t; pos < PH * PW; pos += NT) {
        const int row = pos / PW;
        const int col = pos - row * PW;
        const int hh = h0 + row - RR;
        const int ww = w0p + col - RR;
        const bool sok = ((unsigned)hh < HH) & ((unsigned)ww < WW);
        const float* src = xin + ((size_t)b * DD * HH + hh) * (size_t)WW + ww;

        float buf[PDP];
        #pragma unroll
        for (int p = 0; p < PD; ++p) {
            const int gd = d0 - 1 + p;
            float v = 0.0f;
            if (sok && (unsigned)gd < DD) v = __ldg(src + (size_t)gd * HW);
            buf[p] = v;
        }
        buf[PD] = 0.0f; buf[PD + 1] = 0.0f;

        float4* dst = (float4*)&xs[pos * PDP];
        #pragma unroll
        for (int q = 0; q < PDP / 4; ++q)
            dst[q] = make_float4(buf[4*q], buf[4*q+1], buf[4*q+2], buf[4*q+3]);
    }
    __syncthreads();

    // ---- two vertically adjacent pixels per thread ----
    unsigned long long acc0[DC / 2], acc1[DC / 2];
    #pragma unroll
    for (int k = 0; k < DC / 2; ++k) { acc0[k] = 0ull; acc1[k] = 0ull; }

    // pixel0 tap (i,j) -> slab row 2ty+i ; pixel1 tap (i,j) -> row 2ty+1+i.
    // Flattened taps fi=(i,j), 3-stage rotating weight pipeline (2 ahead).
    #pragma unroll
    for (int fi = 0; fi < KK * (KK + 1); ++fi) {
        const int i = fi / KK;
        const int j = fi - i * KK;

        if (fi + 2 < KK * (KK + 1))
            load_tap(fi + 2, wb0, wb1, P[(fi + 2) % 3]);

        const float* Pc = P[fi % 3];
        unsigned long long W0a = 0, W1a = 0, W2a = 0;
        unsigned long long W0b = 0, W1b = 0, W2b = 0;
        if (i < KK) { W0a = pk2(Pc[0], Pc[0]); W1a = pk2(Pc[1], Pc[1]); W2a = pk2(Pc[2], Pc[2]); }
        if (i >= 1) { W0b = pk2(Pc[3], Pc[3]); W1b = pk2(Pc[4], Pc[4]); W2b = pk2(Pc[5], Pc[5]); }

        // disparity column at compile-time slab offset; sliding 2-quad window
        const float* cb = xsb + (i * PW + j) * PDP;

        Q4 qa, qb; Q2 qt;
        qa.f = *(const float4*)(cb + 0);

        #pragma unroll
        for (int tq = 0; tq < DC / 4; ++tq) {
            // load next quad (or tail pair) of the column
            if (tq < DC / 4 - 1) {
                qb.f = *(const float4*)(cb + 4 * (tq + 1));
            } else {
                qt.f = *(const float2*)(cb + DC);   // c[DC], c[DC+1]
                qb.u[0] = qt.u;
            }
            // k = 2*tq : E=qa.u[0], O=(qa.y,qa.z), E'=qa.u[1]
            {
                const int k = 2 * tq;
                const unsigned long long O = pk2(qa.s[1], qa.s[2]);
                if (i < KK) {
                    ffma2(acc0[k], W1a, qa.u[0]);
                    ffma2(acc0[k], W0a, O);
                    ffma2(acc0[k], W2a, qa.u[1]);
                }
                if (i >= 1) {
                    ffma2(acc1[k], W1b, qa.u[0]);
                    ffma2(acc1[k], W0b, O);
                    ffma2(acc1[k], W2b, qa.u[1]);
                }
            }
            // k = 2*tq+1 : E=qa.u[1], O=(qa.w,qb.x), E'=qb.u[0]
            {
                const int k = 2 * tq + 1;
                const unsigned long long O = pk2(qa.s[3], qb.s[0]);
                if (i < KK) {
                    ffma2(acc0[k], W1a, qa.u[1]);
                    ffma2(acc0[k], W0a, O);
                    ffma2(acc0[k], W2a, qb.u[0]);
                }
                if (i >= 1) {
                    ffma2(acc1[k], W1b, qa.u[1]);
                    ffma2(acc1[k], W0b, O);
                    ffma2(acc1[k], W2b, qb.u[0]);
                }
            }
            if (tq < DC / 4 - 1) {
                qa.f = qb.f;
            }
        }
    }

    // ---- write out (coalesced along tx; guarded for ragged last tile) ----
    float* outp0 = xout + (((size_t)b * DD + d0) * HH + gh0) * (size_t)WW + gw;
    float* outp1 = outp0 + WW;
    #pragma unroll
    for (int k = 0; k < DC / 2; ++k) {
        float lo, hi;
        if (row0ok) {
            upk2(acc0[k], lo, hi);
            outp0[(size_t)(2 * k) * HW]     = lo;
            outp0[(size_t)(2 * k + 1) * HW] = hi;
        }
        if (row1ok) {
            upk2(acc1[k], lo, hi);
            outp1[(size_t)(2 * k) * HW]     = lo;
            outp1[(size_t)(2 * k + 1) * HW] = hi;
        }
    }
}

extern "C" void kernel_launch(void* const* d_in, const int* in_sizes, int n_in,
                              void* d_out, int out_size)
{
    const float* x = (const float*)d_in[0];   // [B, D, H, W]
    const float* w = (const float*)d_in[1];   // [B, 75, H, W]
    float* out = (float*)d_out;

    float* ybuf = nullptr;
    cudaGetSymbolAddress((void**)&ybuf, g_y);

    cudaFuncSetAttribute(lga_kernel,
                         cudaFuncAttributeMaxDynamicSharedMemorySize, SMEM_BYTES);

    // chunk is the fastest grid dimension: blocks 2t and 2t+1 share a tile's
    // weight lines and run in the same wave -> L2 reuse.
    dim3 grid((WW / TW) * NCHUNK, GRID_Y, BB);   // 40 x 27 x 2 = 2160 blocks
    lga_kernel<<<grid, NT, SMEM_BYTES>>>(x, w, ybuf);   // pass 1
    lga_kernel<<<grid, NT, SMEM_BYTES>>>(ybuf, w, out); // pass 2
}

// round 13
// speedup vs baseline: 1.3644x; 1.3644x over previous
#include <cuda_runtime.h>
#include <cstddef>

// Problem constants (fixed by setup_inputs)
#define BB 2
#define DD 48
#define HH 320
#define WW 640
#define RR 2
#define KK 5
#define K2 25
#define HW (HH * WW)

// Tiling: 16x32 output tile, 256 threads, 2 vertical pixels per thread.
// One D-chunk (24 disparities) per block; chunk is the fastest grid dim so
// the two chunks of a tile share weight lines in L2 within the same wave.
#define TH 16
#define TW 32
#define DC 24
#define NCHUNK (DD / DC)   // 2
#define PH (TH + 2 * RR)   // 20
#define PW (TW + 2 * RR)   // 36
#define PD (DC + 2)        // 26 planes used
#define PDP 28             // plane stride (112B -> conflict-free LDS.128)
#define NT 256
#define SMEM_BYTES (PH * PW * PDP * 4)   // 80640
#define NTAPS (KK * (KK + 1))            // 30 flattened (i,j) taps
#define PSTAGES 4                        // weight pipeline depth (3 ahead)

// Intermediate buffer for pass-1 result (allocation-free scratch)
__device__ float g_y[(size_t)BB * DD * HH * WW];

__device__ __forceinline__ unsigned long long pk2(float lo, float hi) {
    unsigned long long r;
    asm("mov.b64 %0, {%1, %2};" : "=l"(r) : "f"(lo), "f"(hi));
    return r;
}
__device__ __forceinline__ void ffma2(unsigned long long &acc,
                                      unsigned long long a,
                                      unsigned long long b) {
    asm("fma.rn.f32x2 %0, %1, %2, %0;" : "+l"(acc) : "l"(a), "l"(b));
}

union Acc { unsigned long long u; float2 f; };
union Q4 { float4 f; unsigned long long u[2]; float s[4]; };
union Q2 { float2 f; unsigned long long u; float s[2]; };

// Load one flattened tap's 6 weights (3 for pixel0 row, 3 for pixel1 row).
// fi is compile-time under full unroll; invalid groups load nothing (stay 0).
__device__ __forceinline__ void load_tap(int fi, const float* wb0,
                                         const float* wb1, float* P)
{
    const int i = fi / KK;
    const int j = fi - i * KK;
    P[0] = 0.f; P[1] = 0.f; P[2] = 0.f; P[3] = 0.f; P[4] = 0.f; P[5] = 0.f;
    if (i < KK) {            // pixel0 tap (i, j)
        P[0] = __ldg(wb0 + (size_t)(0 * K2 + i * KK + j) * HW);
        P[1] = __ldg(wb0 + (size_t)(1 * K2 + i * KK + j) * HW);
        P[2] = __ldg(wb0 + (size_t)(2 * K2 + i * KK + j) * HW);
    }
    if (i >= 1) {            // pixel1 tap (i-1, j)
        P[3] = __ldg(wb1 + (size_t)(0 * K2 + (i - 1) * KK + j) * HW);
        P[4] = __ldg(wb1 + (size_t)(1 * K2 + (i - 1) * KK + j) * HW);
        P[5] = __ldg(wb1 + (size_t)(2 * K2 + (i - 1) * KK + j) * HW);
    }
}

__global__ void __launch_bounds__(NT, 2)
lga_kernel(const float* __restrict__ xin,
           const float* __restrict__ wts,
           float* __restrict__ xout)
{
    extern __shared__ float xs[];   // [PH][PW][PDP]

    const int t  = threadIdx.x;
    const int tx = t & 31;       // W within tile
    const int ty = t >> 5;       // 0..7 -> output rows 2ty, 2ty+1

    const int bx    = blockIdx.x;
    const int chunk = bx & 1;            // fastest dim: chunks of a tile adjacent
    const int w0p   = (bx >> 1) * TW;
    const int h0    = blockIdx.y * TH;
    const int b     = blockIdx.z;
    const int d0    = chunk * DC;

    const int gh0 = h0 + 2 * ty;
    const int gw  = w0p + tx;

    // weight base: wts[b, c, gh, gw], channel stride = HW
    const float* wb0 = wts + ((size_t)b * (3 * K2)) * HW + (size_t)gh0 * WW + gw;
    const float* wb1 = wb0 + WW;   // row gh0+1

    // thread's column base in the slab; per-tap offset is a compile-time const
    float* const xsb = &xs[(2 * ty * PW + tx) * PDP];

    // ---- prime the 4-stage weight pipeline BEFORE the fill (overlap) ----
    float P[PSTAGES][6];
    load_tap(0, wb0, wb1, P[0]);
    load_tap(1, wb0, wb1, P[1]);
    load_tap(2, wb0, wb1, P[2]);

    // ---- fill shared slab, plane-contiguous: xs[(row*PW+col)*PDP + p] ----
    for (int pos = t; pos < PH * PW; pos += NT) {
        const int row = pos / PW;
        const int col = pos - row * PW;
        const int hh = h0 + row - RR;
        const int ww = w0p + col - RR;
        const bool sok = ((unsigned)hh < HH) & ((unsigned)ww < WW);
        const float* src = xin + ((size_t)b * DD * HH + hh) * (size_t)WW + ww;

        float buf[PDP];
        #pragma unroll
        for (int p = 0; p < PD; ++p) {
            const int gd = d0 - 1 + p;
            float v = 0.0f;
            if (sok && (unsigned)gd < DD) v = __ldg(src + (size_t)gd * HW);
            buf[p] = v;
        }
        buf[PD] = 0.0f; buf[PD + 1] = 0.0f;

        float4* dst = (float4*)&xs[pos * PDP];
        #pragma unroll
        for (int q = 0; q < PDP / 4; ++q)
            dst[q] = make_float4(buf[4*q], buf[4*q+1], buf[4*q+2], buf[4*q+3]);
    }
    __syncthreads();

    // ---- two vertically adjacent pixels per thread ----
    Acc acc0[DC / 2], acc1[DC / 2];
    #pragma unroll
    for (int k = 0; k < DC / 2; ++k) { acc0[k].u = 0ull; acc1[k].u = 0ull; }

    // pixel0 tap (i,j) -> slab row 2ty+i ; pixel1 tap (i,j) -> row 2ty+1+i.
    // W1/W2 groups use aligned packed pairs (FFMA2); the W0 group (odd
    // alignment) uses scalar FFMAs into the pair halves -> no pack movs.
    #pragma unroll
    for (int fi = 0; fi < NTAPS; ++fi) {
        const int i = fi / KK;
        const int j = fi - i * KK;

        if (fi + 3 < NTAPS)
            load_tap(fi + 3, wb0, wb1, P[(fi + 3) % PSTAGES]);

        const float* Pc = P[fi % PSTAGES];
        // packed weights for the aligned groups only
        unsigned long long W1a = 0, W2a = 0, W1b = 0, W2b = 0;
        float w0a = 0.f, w0b = 0.f;
        if (i < KK) { w0a = Pc[0]; W1a = pk2(Pc[1], Pc[1]); W2a = pk2(Pc[2], Pc[2]); }
        if (i >= 1) { w0b = Pc[3]; W1b = pk2(Pc[4], Pc[4]); W2b = pk2(Pc[5], Pc[5]); }

        // disparity column at compile-time slab offset; sliding 2-quad window
        const float* cb = xsb + (i * PW + j) * PDP;

        Q4 qa, qb; Q2 qt;
        qa.f = *(const float4*)(cb + 0);

        #pragma unroll
        for (int tq = 0; tq < DC / 4; ++tq) {
            // load next quad (or tail pair) of the column
            if (tq < DC / 4 - 1) {
                qb.f = *(const float4*)(cb + 4 * (tq + 1));
            } else {
                qt.f = *(const float2*)(cb + DC);   // c[DC], c[DC+1]
                qb.u[0] = qt.u;
            }
            // pair k = 2*tq : d=(4tq,4tq+1); x[d-1..]=E=qa.u[0], x[d+1..]=qa.u[1]
            // W0 scalars: x[d]=c[4tq+1]=qa.s[1], c[4tq+2]=qa.s[2]
            {
                const int k = 2 * tq;
                if (i < KK) {
                    ffma2(acc0[k].u, W1a, qa.u[0]);
                    acc0[k].f.x = fmaf(w0a, qa.s[1], acc0[k].f.x);
                    acc0[k].f.y = fmaf(w0a, qa.s[2], acc0[k].f.y);
                    ffma2(acc0[k].u, W2a, qa.u[1]);
                }
                if (i >= 1) {
                    ffma2(acc1[k].u, W1b, qa.u[0]);
                    acc1[k].f.x = fmaf(w0b, qa.s[1], acc1[k].f.x);
                    acc1[k].f.y = fmaf(w0b, qa.s[2], acc1[k].f.y);
                    ffma2(acc1[k].u, W2b, qa.u[1]);
                }
            }
            // pair k = 2*tq+1 : W0 scalars use c[4tq+3]=qa.s[3], c[4tq+4]=qb.s[0]
            {
                const int k = 2 * tq + 1;
                if (i < KK) {
                    ffma2(acc0[k].u, W1a, qa.u[1]);
                    acc0[k].f.x = fmaf(w0a, qa.s[3], acc0[k].f.x);
                    acc0[k].f.y = fmaf(w0a, qb.s[0], acc0[k].f.y);
                    ffma2(acc0[k].u, W2a, qb.u[0]);
                }
                if (i >= 1) {
                    ffma2(acc1[k].u, W1b, qa.u[1]);
                    acc1[k].f.x = fmaf(w0b, qa.s[3], acc1[k].f.x);
                    acc1[k].f.y = fmaf(w0b, qb.s[0], acc1[k].f.y);
                    ffma2(acc1[k].u, W2b, qb.u[0]);
                }
            }
            if (tq < DC / 4 - 1) {
                qa.f = qb.f;
            }
        }
    }

    // ---- write out (coalesced along tx) ----
    float* outp0 = xout + (((size_t)b * DD + d0) * HH + gh0) * (size_t)WW + gw;
    float* outp1 = outp0 + WW;
    #pragma unroll
    for (int k = 0; k < DC / 2; ++k) {
        outp0[(size_t)(2 * k) * HW]     = acc0[k].f.x;
        outp0[(size_t)(2 * k + 1) * HW] = acc0[k].f.y;
        outp1[(size_t)(2 * k) * HW]     = acc1[k].f.x;
        outp1[(size_t)(2 * k + 1) * HW] = acc1[k].f.y;
    }
}

extern "C" void kernel_launch(void* const* d_in, const int* in_sizes, int n_in,
                              void* d_out, int out_size)
{
    const float* x = (const float*)d_in[0];   // [B, D, H, W]
    const float* w = (const float*)d_in[1];   // [B, 75, H, W]
    float* out = (float*)d_out;

    float* ybuf = nullptr;
    cudaGetSymbolAddress((void**)&ybuf, g_y);

    cudaFuncSetAttribute(lga_kernel,
                         cudaFuncAttributeMaxDynamicSharedMemorySize, SMEM_BYTES);

    // chunk is the fastest grid dimension: blocks 2t and 2t+1 share a tile's
    // weight lines and run in the same wave -> L2 reuse.
    dim3 grid((WW / TW) * NCHUNK, HH / TH, BB);   // 40 x 20 x 2
    lga_kernel<<<grid, NT, SMEM_BYTES>>>(x, w, ybuf);   // pass 1
    lga_kernel<<<grid, NT, SMEM_BYTES>>>(ybuf, w, out); // pass 2
}